// round 2
// baseline (speedup 1.0000x reference)
#include <cuda_runtime.h>

#define BATCH 8
#define SEQ   4096
#define DM    1024
#define CHUNK 256
#define NC    (SEQ / CHUNK)   // 16

// ---------------- scratch (device globals; no runtime allocation) ----------
__device__ float g_S[(size_t)BATCH * SEQ * DM];        // EMA states, 128 MB
__device__ float g_partial[BATCH * NC * DM];            // per-chunk local scan ends
__device__ float g_carry[BATCH * NC * DM];              // per-chunk incoming state

static __device__ __forceinline__ float sigmoidf_(float v) {
    return 1.0f / (1.0f + expf(-v));
}

// ---------------- Phase A: per-chunk local EMA (zero-seeded) ---------------
__global__ void ema_partial_kernel(const float* __restrict__ x,
                                   const float* __restrict__ dl) {
    const int d  = threadIdx.x;          // 0..1023
    const int bc = blockIdx.x;           // b*NC + c
    const int b  = bc / NC;
    const int c  = bc % NC;
    const float a  = sigmoidf_(dl[d]);
    const float om = 1.0f - a;
    const float* xp = x + ((size_t)b * SEQ + (size_t)c * CHUNK) * DM + d;
    float s = 0.0f;
#pragma unroll 4
    for (int i = 0; i < CHUNK; i++) {
        s = a * s + om * xp[(size_t)i * DM];
    }
    g_partial[(size_t)bc * DM + d] = s;
}

// ---------------- Phase B: combine carries across chunks -------------------
__global__ void ema_carry_kernel(const float* __restrict__ dl) {
    const int d = threadIdx.x;
    const int b = blockIdx.x;
    const float a = sigmoidf_(dl[d]);
    float pw = a;                         // a^(2^8) = a^CHUNK via 8 squarings
#pragma unroll
    for (int i = 0; i < 8; i++) pw *= pw;
    float cur = 0.0f;
    for (int c = 0; c < NC; c++) {
        const size_t idx = ((size_t)b * NC + c) * DM + d;
        g_carry[idx] = cur;
        cur = pw * cur + g_partial[idx];
    }
}

// ---------------- Phase C: seeded rescan, write S --------------------------
__global__ void ema_final_kernel(const float* __restrict__ x,
                                 const float* __restrict__ dl) {
    const int d  = threadIdx.x;
    const int bc = blockIdx.x;
    const int b  = bc / NC;
    const int c  = bc % NC;
    const float a  = sigmoidf_(dl[d]);
    const float om = 1.0f - a;
    float s = g_carry[(size_t)bc * DM + d];
    const float* xp = x   + ((size_t)b * SEQ + (size_t)c * CHUNK) * DM + d;
    float*       sp = g_S + ((size_t)b * SEQ + (size_t)c * CHUNK) * DM + d;
#pragma unroll 4
    for (int i = 0; i < CHUNK; i++) {
        s = a * s + om * xp[(size_t)i * DM];
        sp[(size_t)i * DM] = s;
    }
}

// ---------------- GEMM (S @ W^T) + bias + fused depthwise conv -------------
#define BM 128
#define BN 128
#define BK 16

__global__ __launch_bounds__(256)
void gemm_conv_kernel(const float* __restrict__ W,
                      const float* __restrict__ bias,
                      const float* __restrict__ x,
                      const float* __restrict__ conv_w,
                      const float* __restrict__ conv_b,
                      float* __restrict__ out) {
    __shared__ float As[BK][BM];
    __shared__ float Bs[BK][BN];

    const int tid = threadIdx.x;
    const int tx  = tid % 16;
    const int ty  = tid / 16;
    const int bx  = blockIdx.x;      // N tiles (8)
    const int by  = blockIdx.y;      // M tiles (256)

    const float* A  = g_S + (size_t)by * BM * DM;  // S rows m = by*128 ..
    const float* Bw = W   + (size_t)bx * BN * DM;  // W rows e = bx*128 ..

    const int lr = tid >> 2;          // 0..63 (row within tile)
    const int lk = (tid & 3) * 4;     // 0,4,8,12 (k within tile)

    float acc[8][8];
#pragma unroll
    for (int i = 0; i < 8; i++)
#pragma unroll
        for (int j = 0; j < 8; j++) acc[i][j] = 0.0f;

    for (int kt = 0; kt < DM; kt += BK) {
        const float4 a0 = *(const float4*)(A  + (size_t)lr        * DM + kt + lk);
        const float4 a1 = *(const float4*)(A  + (size_t)(lr + 64) * DM + kt + lk);
        const float4 b0 = *(const float4*)(Bw + (size_t)lr        * DM + kt + lk);
        const float4 b1 = *(const float4*)(Bw + (size_t)(lr + 64) * DM + kt + lk);

        As[lk + 0][lr]      = a0.x; As[lk + 1][lr]      = a0.y;
        As[lk + 2][lr]      = a0.z; As[lk + 3][lr]      = a0.w;
        As[lk + 0][lr + 64] = a1.x; As[lk + 1][lr + 64] = a1.y;
        As[lk + 2][lr + 64] = a1.z; As[lk + 3][lr + 64] = a1.w;
        Bs[lk + 0][lr]      = b0.x; Bs[lk + 1][lr]      = b0.y;
        Bs[lk + 2][lr]      = b0.z; Bs[lk + 3][lr]      = b0.w;
        Bs[lk + 0][lr + 64] = b1.x; Bs[lk + 1][lr + 64] = b1.y;
        Bs[lk + 2][lr + 64] = b1.z; Bs[lk + 3][lr + 64] = b1.w;
        __syncthreads();

#pragma unroll
        for (int k = 0; k < BK; k++) {
            float ar[8], br[8];
            *(float4*)(ar)     = *(const float4*)&As[k][ty * 8];
            *(float4*)(ar + 4) = *(const float4*)&As[k][ty * 8 + 4];
            *(float4*)(br)     = *(const float4*)&Bs[k][tx * 8];
            *(float4*)(br + 4) = *(const float4*)&Bs[k][tx * 8 + 4];
#pragma unroll
            for (int i = 0; i < 8; i++)
#pragma unroll
                for (int j = 0; j < 8; j++)
                    acc[i][j] += ar[i] * br[j];
        }
        __syncthreads();
    }

    // ---- epilogue: + bias + depthwise conv(x, K=5, same pad) + conv_b ----
    const int b_  = by / (SEQ / BM);             // batch (tile never crosses batch)
    const int t0  = (by % (SEQ / BM)) * BM + ty * 8;
    const int e0  = bx * BN + tx * 8;

    float cw[8][5], cb8[8], bi8[8];
#pragma unroll
    for (int j = 0; j < 8; j++) {
        const int e = e0 + j;
        bi8[j] = __ldg(&bias[e]);
        cb8[j] = __ldg(&conv_b[e]);
#pragma unroll
        for (int k = 0; k < 5; k++) cw[j][k] = __ldg(&conv_w[e * 5 + k]);
    }

    const float* xb = x + (size_t)b_ * SEQ * DM;

#pragma unroll
    for (int i = 0; i < 8; i++) {
        const int t = t0 + i;
        float r[8];
#pragma unroll
        for (int j = 0; j < 8; j++) r[j] = acc[i][j] + bi8[j] + cb8[j];

#pragma unroll
        for (int k = 0; k < 5; k++) {
            const int tt = t - 2 + k;
            if (tt >= 0 && tt < SEQ) {
                float xv[8];
                *(float4*)(xv)     = *(const float4*)(xb + (size_t)tt * DM + e0);
                *(float4*)(xv + 4) = *(const float4*)(xb + (size_t)tt * DM + e0 + 4);
#pragma unroll
                for (int j = 0; j < 8; j++) r[j] += cw[j][k] * xv[j];
            }
        }

        float* op = out + ((size_t)b_ * SEQ + (size_t)t) * DM + e0;
        *(float4*)(op)     = make_float4(r[0], r[1], r[2], r[3]);
        *(float4*)(op + 4) = make_float4(r[4], r[5], r[6], r[7]);
    }
}

// ---------------------------------------------------------------------------
extern "C" void kernel_launch(void* const* d_in, const int* in_sizes, int n_in,
                              void* d_out, int out_size) {
    const float* x      = (const float*)d_in[0];
    const float* dl     = (const float*)d_in[1];
    const float* W      = (const float*)d_in[2];
    const float* bias   = (const float*)d_in[3];
    const float* conv_w = (const float*)d_in[4];
    const float* conv_b = (const float*)d_in[5];
    float* out = (float*)d_out;

    ema_partial_kernel<<<BATCH * NC, DM>>>(x, dl);
    ema_carry_kernel<<<BATCH, DM>>>(dl);
    ema_final_kernel<<<BATCH * NC, DM>>>(x, dl);

    dim3 grid(DM / BN, (BATCH * SEQ) / BM);   // (8, 256): N fastest for L2 A-reuse
    gemm_conv_kernel<<<grid, 256>>>(W, bias, x, conv_w, conv_b, out);
}

// round 4
// speedup vs baseline: 2.5477x; 2.5477x over previous
#include <cuda_runtime.h>
#include <cuda_bf16.h>
#include <cstdint>

#define BATCH 8
#define SEQ   4096
#define DM    1024
#define CHUNK 256
#define NC    (SEQ / CHUNK)   // 16

// GEMM tiling
#define TM 128
#define TN 128
#define KC 64                  // bf16 per K stage = 128 bytes per row
#define NKC (DM / KC)          // 16 stages
#define NTHREADS 256

// smem stage layout (per buffer): Ahi | Alo | Bhi | Blo, 16KB each
#define A_HI  0
#define A_LO  16384
#define B_HI  32768
#define B_LO  49152
#define STAGE 65536
#define SMEM_DYN (2 * STAGE)

// ---------------- scratch (device globals; no runtime allocation) ----------
__device__ __nv_bfloat16 g_Shi[(size_t)BATCH * SEQ * DM];
__device__ __nv_bfloat16 g_Slo[(size_t)BATCH * SEQ * DM];
__device__ __nv_bfloat16 g_Whi[DM * DM];
__device__ __nv_bfloat16 g_Wlo[DM * DM];
__device__ float g_partial[BATCH * NC * DM];
__device__ float g_carry[BATCH * NC * DM];

static __device__ __forceinline__ float sigmoidf_(float v) {
    return 1.0f / (1.0f + expf(-v));
}

// ====================== baseline-PTX helpers (no 'a' features) ==============
__device__ __forceinline__ uint32_t smem_u32(const void* p) {
    uint32_t a;
    asm("{ .reg .u64 t; cvta.to.shared.u64 t, %1; cvt.u32.u64 %0, t; }" : "=r"(a) : "l"(p));
    return a;
}

__device__ __forceinline__ void cp16(uint32_t dst, const void* src) {
    asm volatile("cp.async.cg.shared.global [%0], [%1], 16;"
                 :: "r"(dst), "l"(src) : "memory");
}
#define CP_COMMIT() asm volatile("cp.async.commit_group;" ::: "memory")
#define CP_WAIT(n)  asm volatile("cp.async.wait_group %0;" :: "n"(n) : "memory")

__device__ __forceinline__ void ldsm_x4(uint32_t* r, uint32_t addr) {
    asm volatile("ldmatrix.sync.aligned.m8n8.x4.shared.b16 {%0,%1,%2,%3}, [%4];"
                 : "=r"(r[0]), "=r"(r[1]), "=r"(r[2]), "=r"(r[3]) : "r"(addr));
}

__device__ __forceinline__ void mma_bf16(float* c, const uint32_t* a, const uint32_t* b) {
    asm volatile(
        "mma.sync.aligned.m16n8k16.row.col.f32.bf16.bf16.f32 "
        "{%0,%1,%2,%3}, {%4,%5,%6,%7}, {%8,%9}, {%0,%1,%2,%3};"
        : "+f"(c[0]), "+f"(c[1]), "+f"(c[2]), "+f"(c[3])
        : "r"(a[0]), "r"(a[1]), "r"(a[2]), "r"(a[3]), "r"(b[0]), "r"(b[1]));
}

// ====================== EMA (3-phase chunked scan) ==========================
__global__ void ema_partial_kernel(const float* __restrict__ x,
                                   const float* __restrict__ dl) {
    const int d  = threadIdx.x;
    const int bc = blockIdx.x;
    const int b  = bc / NC;
    const int c  = bc % NC;
    const float a  = sigmoidf_(dl[d]);
    const float om = 1.0f - a;
    const float* xp = x + ((size_t)b * SEQ + (size_t)c * CHUNK) * DM + d;
    float s = 0.0f;
#pragma unroll 4
    for (int i = 0; i < CHUNK; i++) s = a * s + om * xp[(size_t)i * DM];
    g_partial[(size_t)bc * DM + d] = s;
}

__global__ void ema_carry_kernel(const float* __restrict__ dl) {
    const int d = threadIdx.x;
    const int b = blockIdx.x;
    const float a = sigmoidf_(dl[d]);
    float pw = a;
#pragma unroll
    for (int i = 0; i < 8; i++) pw *= pw;   // a^256
    float cur = 0.0f;
    for (int c = 0; c < NC; c++) {
        const size_t idx = ((size_t)b * NC + c) * DM + d;
        g_carry[idx] = cur;
        cur = pw * cur + g_partial[idx];
    }
}

__global__ void ema_final_kernel(const float* __restrict__ x,
                                 const float* __restrict__ dl) {
    const int d  = threadIdx.x;
    const int bc = blockIdx.x;
    const int b  = bc / NC;
    const int c  = bc % NC;
    const float a  = sigmoidf_(dl[d]);
    const float om = 1.0f - a;
    float s = g_carry[(size_t)bc * DM + d];
    const size_t base = ((size_t)b * SEQ + (size_t)c * CHUNK) * DM + d;
    const float* xp = x + base;
#pragma unroll 4
    for (int i = 0; i < CHUNK; i++) {
        s = a * s + om * xp[(size_t)i * DM];
        __nv_bfloat16 h = __float2bfloat16_rn(s);
        g_Shi[base + (size_t)i * DM] = h;
        g_Slo[base + (size_t)i * DM] = __float2bfloat16_rn(s - __bfloat162float(h));
    }
}

__global__ void wsplit_kernel(const float* __restrict__ W) {
    const int i = blockIdx.x * blockDim.x + threadIdx.x;
    const float w = W[i];
    const __nv_bfloat16 h = __float2bfloat16_rn(w);
    g_Whi[i] = h;
    g_Wlo[i] = __float2bfloat16_rn(w - __bfloat162float(h));
}

// ====================== HMMA GEMM + fused conv epilogue =====================
// copy one 128-row x 128-byte tile (gmem row stride 2048B) into swizzled smem
__device__ __forceinline__ void copy_tile_async(const char* __restrict__ src,
                                                uint32_t dst, int tid) {
#pragma unroll
    for (int i = 0; i < 4; i++) {
        const int idx = tid + i * NTHREADS;     // 0..1023
        const int row = idx >> 3;
        const int seg = idx & 7;
        uint32_t off = (uint32_t)((row << 7) + (seg << 4));
        off ^= (uint32_t)((row & 7) << 4);      // SW128-style
        cp16(dst + off, src + (size_t)row * (DM * 2) + (seg << 4));
    }
}

__global__ __launch_bounds__(NTHREADS, 1)
void gemm_mma_kernel(const float* __restrict__ x,
                     const float* __restrict__ bias,
                     const float* __restrict__ conv_w,
                     const float* __restrict__ conv_b,
                     float* __restrict__ out) {
    extern __shared__ char dsm[];
    __shared__ float s_bias2[TN];
    __shared__ float s_cw[TN * 5];

    const int tid  = threadIdx.x;
    const int wid  = tid >> 5;
    const int lane = tid & 31;

    const int n0 = blockIdx.x * TN;          // output-channel base
    const int m0 = blockIdx.y * TM;          // flattened (b*SEQ + t) base
    const int b_ = m0 >> 12;
    const int t0 = m0 & (SEQ - 1);

    const int wm = (wid & 1) * 64;           // warp M offset (2 warps in M)
    const int wn = (wid >> 1) * 32;          // warp N offset (4 warps in N)

    const uint32_t sbase = smem_u32(dsm);

    // epilogue constants
    for (int i = tid; i < TN; i += NTHREADS) {
        const int e = n0 + i;
        s_bias2[i] = bias[e] + conv_b[e];
#pragma unroll
        for (int k = 0; k < 5; k++) s_cw[i * 5 + k] = conv_w[e * 5 + k];
    }

    const char* Ahi = (const char*)(g_Shi + (size_t)m0 * DM);
    const char* Alo = (const char*)(g_Slo + (size_t)m0 * DM);
    const char* Bhi = (const char*)(g_Whi + (size_t)n0 * DM);
    const char* Blo = (const char*)(g_Wlo + (size_t)n0 * DM);

    float acc[4][4][4];
#pragma unroll
    for (int mt = 0; mt < 4; mt++)
#pragma unroll
        for (int nt = 0; nt < 4; nt++)
#pragma unroll
            for (int k = 0; k < 4; k++) acc[mt][nt][k] = 0.0f;

    // ldmatrix lane constants
    const int lr = lane & 15;
    const int lh = lane >> 4;
    const uint32_t xorv = (uint32_t)((lr & 7) << 4);

    // prologue: stage 0
    copy_tile_async(Ahi, sbase + A_HI, tid);
    copy_tile_async(Alo, sbase + A_LO, tid);
    copy_tile_async(Bhi, sbase + B_HI, tid);
    copy_tile_async(Blo, sbase + B_LO, tid);
    CP_COMMIT();

#pragma unroll 1
    for (int kc = 0; kc < NKC; kc++) {
        if (kc + 1 < NKC) {
            const uint32_t nb = sbase + (uint32_t)((kc + 1) & 1) * STAGE;
            const size_t co = (size_t)(kc + 1) * 128;   // byte col offset
            copy_tile_async(Ahi + co, nb + A_HI, tid);
            copy_tile_async(Alo + co, nb + A_LO, tid);
            copy_tile_async(Bhi + co, nb + B_HI, tid);
            copy_tile_async(Blo + co, nb + B_LO, tid);
            CP_COMMIT();
            CP_WAIT(1);
        } else {
            CP_WAIT(0);
        }
        __syncthreads();

        const uint32_t sb = sbase + (uint32_t)(kc & 1) * STAGE;

#pragma unroll
        for (int ks = 0; ks < 4; ks++) {
            uint32_t ah[4][4], al[4][4], bh[4][2], bl[4][2];
#pragma unroll
            for (int mt = 0; mt < 4; mt++) {
                const uint32_t row = (uint32_t)(wm + mt * 16 + lr);
                uint32_t off = (row << 7) + (uint32_t)(ks * 32 + (lh << 4));
                off ^= xorv;
                ldsm_x4(ah[mt], sb + A_HI + off);
                ldsm_x4(al[mt], sb + A_LO + off);
            }
#pragma unroll
            for (int p = 0; p < 2; p++) {
                const uint32_t row = (uint32_t)(wn + p * 16 + lr);
                uint32_t off = (row << 7) + (uint32_t)(ks * 32 + (lh << 4));
                off ^= xorv;
                uint32_t r0[4], r1[4];
                ldsm_x4(r0, sb + B_HI + off);
                bh[2 * p][0] = r0[0]; bh[2 * p][1] = r0[2];
                bh[2 * p + 1][0] = r0[1]; bh[2 * p + 1][1] = r0[3];
                ldsm_x4(r1, sb + B_LO + off);
                bl[2 * p][0] = r1[0]; bl[2 * p][1] = r1[2];
                bl[2 * p + 1][0] = r1[1]; bl[2 * p + 1][1] = r1[3];
            }
#pragma unroll
            for (int mt = 0; mt < 4; mt++)
#pragma unroll
                for (int nt = 0; nt < 4; nt++) {
                    float* c = acc[mt][nt];
                    mma_bf16(c, ah[mt], bh[nt]);
                    mma_bf16(c, al[mt], bh[nt]);
                    mma_bf16(c, ah[mt], bl[nt]);
                }
        }
        __syncthreads();
    }

    // --- epilogue: + bias + conv_b + depthwise conv(x, K=5), write out -----
    const int lq = lane >> 2;        // 0..7
    const int lc = (lane & 3) * 2;   // col pair within n8 tile
    const float* xb = x + (size_t)b_ * SEQ * DM;

#pragma unroll
    for (int mt = 0; mt < 4; mt++) {
#pragma unroll
        for (int half = 0; half < 2; half++) {
            const int t = t0 + wm + mt * 16 + lq + half * 8;
            float2 v[4];
#pragma unroll
            for (int nt = 0; nt < 4; nt++) {
                const int ei = wn + nt * 8 + lc;   // index into TN
                v[nt].x = acc[mt][nt][half * 2 + 0] + s_bias2[ei];
                v[nt].y = acc[mt][nt][half * 2 + 1] + s_bias2[ei + 1];
            }
#pragma unroll
            for (int k = 0; k < 5; k++) {
                const int tt = t - 2 + k;
                if (tt >= 0 && tt < SEQ) {
                    const float* xr = xb + (size_t)tt * DM + n0;
#pragma unroll
                    for (int nt = 0; nt < 4; nt++) {
                        const int ei = wn + nt * 8 + lc;
                        const float2 xv = *(const float2*)(xr + ei);
                        v[nt].x += s_cw[ei * 5 + k] * xv.x;
                        v[nt].y += s_cw[(ei + 1) * 5 + k] * xv.y;
                    }
                }
            }
            float* op = out + ((size_t)b_ * SEQ + (size_t)t) * DM + n0;
#pragma unroll
            for (int nt = 0; nt < 4; nt++)
                *(float2*)(op + wn + nt * 8 + lc) = v[nt];
        }
    }
}

// ---------------------------------------------------------------------------
extern "C" void kernel_launch(void* const* d_in, const int* in_sizes, int n_in,
                              void* d_out, int out_size) {
    const float* x      = (const float*)d_in[0];
    const float* dl     = (const float*)d_in[1];
    const float* W      = (const float*)d_in[2];
    const float* bias   = (const float*)d_in[3];
    const float* conv_w = (const float*)d_in[4];
    const float* conv_b = (const float*)d_in[5];
    float* out = (float*)d_out;

    cudaFuncSetAttribute(gemm_mma_kernel,
                         cudaFuncAttributeMaxDynamicSharedMemorySize, SMEM_DYN);

    wsplit_kernel<<<(DM * DM) / 256, 256>>>(W);
    ema_partial_kernel<<<BATCH * NC, DM>>>(x, dl);
    ema_carry_kernel<<<BATCH, DM>>>(dl);
    ema_final_kernel<<<BATCH * NC, DM>>>(x, dl);

    dim3 grid(DM / TN, (BATCH * SEQ) / TM);   // (8, 256)
    gemm_mma_kernel<<<grid, NTHREADS, SMEM_DYN>>>(x, bias, conv_w, conv_b, out);
}

// round 5
// speedup vs baseline: 2.8835x; 1.1318x over previous
#include <cuda_runtime.h>
#include <cuda_bf16.h>
#include <cstdint>

#define BATCH 8
#define SEQ   4096
#define DM    1024
#define CHUNK 128
#define NC    (SEQ / CHUNK)   // 32

// GEMM tiling: CTA 128x256, warp 64x64 (2M x 4N warps)
#define TM 128
#define TN 256
#define KC 64                  // bf16 per K stage = 128 bytes per row
#define NKC (DM / KC)          // 16 stages
#define NTHREADS 256

// smem stage layout (per buffer): Ahi 16K | Alo 16K | Bhi 32K | Blo 32K
#define A_HI  0
#define A_LO  16384
#define B_HI  32768
#define B_LO  65536
#define STAGE 98304
#define SMEM_DYN (2 * STAGE)   // 192 KB

// ---------------- scratch (device globals; no runtime allocation) ----------
__device__ __nv_bfloat16 g_Shi[(size_t)BATCH * SEQ * DM];
__device__ __nv_bfloat16 g_Slo[(size_t)BATCH * SEQ * DM];
__device__ __nv_bfloat16 g_Whi[DM * DM];
__device__ __nv_bfloat16 g_Wlo[DM * DM];
__device__ float g_partial[BATCH * NC * DM];
__device__ float g_carry[BATCH * NC * DM];

static __device__ __forceinline__ float sigmoidf_(float v) {
    return 1.0f / (1.0f + expf(-v));
}

// ====================== baseline-PTX helpers ================================
__device__ __forceinline__ uint32_t smem_u32(const void* p) {
    uint32_t a;
    asm("{ .reg .u64 t; cvta.to.shared.u64 t, %1; cvt.u32.u64 %0, t; }" : "=r"(a) : "l"(p));
    return a;
}

__device__ __forceinline__ void cp16(uint32_t dst, const void* src) {
    asm volatile("cp.async.cg.shared.global [%0], [%1], 16;"
                 :: "r"(dst), "l"(src) : "memory");
}
#define CP_COMMIT() asm volatile("cp.async.commit_group;" ::: "memory")
#define CP_WAIT(n)  asm volatile("cp.async.wait_group %0;" :: "n"(n) : "memory")

__device__ __forceinline__ void ldsm_x4(uint32_t* r, uint32_t addr) {
    asm volatile("ldmatrix.sync.aligned.m8n8.x4.shared.b16 {%0,%1,%2,%3}, [%4];"
                 : "=r"(r[0]), "=r"(r[1]), "=r"(r[2]), "=r"(r[3]) : "r"(addr));
}

__device__ __forceinline__ void mma_bf16(float* c, const uint32_t* a, const uint32_t* b) {
    asm volatile(
        "mma.sync.aligned.m16n8k16.row.col.f32.bf16.bf16.f32 "
        "{%0,%1,%2,%3}, {%4,%5,%6,%7}, {%8,%9}, {%0,%1,%2,%3};"
        : "+f"(c[0]), "+f"(c[1]), "+f"(c[2]), "+f"(c[3])
        : "r"(a[0]), "r"(a[1]), "r"(a[2]), "r"(a[3]), "r"(b[0]), "r"(b[1]));
}

// ====================== EMA (3-phase chunked scan) ==========================
__global__ void ema_partial_kernel(const float* __restrict__ x,
                                   const float* __restrict__ dl) {
    const int d  = threadIdx.x;
    const int bc = blockIdx.x;
    const int b  = bc / NC;
    const int c  = bc % NC;
    const float a  = sigmoidf_(dl[d]);
    const float om = 1.0f - a;
    const float* xp = x + ((size_t)b * SEQ + (size_t)c * CHUNK) * DM + d;
    float s = 0.0f;
#pragma unroll 4
    for (int i = 0; i < CHUNK; i++) s = a * s + om * xp[(size_t)i * DM];
    g_partial[(size_t)bc * DM + d] = s;
}

__global__ void ema_carry_kernel(const float* __restrict__ dl) {
    const int d = threadIdx.x;
    const int b = blockIdx.x;
    const float a = sigmoidf_(dl[d]);
    float pw = a;
#pragma unroll
    for (int i = 0; i < 7; i++) pw *= pw;   // a^(2^7) = a^CHUNK
    float cur = 0.0f;
    for (int c = 0; c < NC; c++) {
        const size_t idx = ((size_t)b * NC + c) * DM + d;
        g_carry[idx] = cur;
        cur = pw * cur + g_partial[idx];
    }
}

__global__ void ema_final_kernel(const float* __restrict__ x,
                                 const float* __restrict__ dl) {
    const int d  = threadIdx.x;
    const int bc = blockIdx.x;
    const int b  = bc / NC;
    const int c  = bc % NC;
    const float a  = sigmoidf_(dl[d]);
    const float om = 1.0f - a;
    float s = g_carry[(size_t)bc * DM + d];
    const size_t base = ((size_t)b * SEQ + (size_t)c * CHUNK) * DM + d;
    const float* xp = x + base;
#pragma unroll 4
    for (int i = 0; i < CHUNK; i++) {
        s = a * s + om * xp[(size_t)i * DM];
        __nv_bfloat16 h = __float2bfloat16_rn(s);
        g_Shi[base + (size_t)i * DM] = h;
        g_Slo[base + (size_t)i * DM] = __float2bfloat16_rn(s - __bfloat162float(h));
    }
}

__global__ void wsplit_kernel(const float* __restrict__ W) {
    const int i = blockIdx.x * blockDim.x + threadIdx.x;
    const float w = W[i];
    const __nv_bfloat16 h = __float2bfloat16_rn(w);
    g_Whi[i] = h;
    g_Wlo[i] = __float2bfloat16_rn(w - __bfloat162float(h));
}

// ====================== HMMA GEMM + fused conv epilogue =====================
// copy `rows` rows of 128 bytes (gmem row stride 2048B) into swizzled smem
__device__ __forceinline__ void copy_tile_async(const char* __restrict__ src,
                                                uint32_t dst, int rows, int tid) {
    const int n = rows * 8;
#pragma unroll
    for (int idx = tid; idx < n; idx += NTHREADS) {
        const int row = idx >> 3;
        const int seg = idx & 7;
        uint32_t off = (uint32_t)((row << 7) + (seg << 4));
        off ^= (uint32_t)((row & 7) << 4);      // SW128-style
        cp16(dst + off, src + (size_t)row * (DM * 2) + (seg << 4));
    }
}

__global__ __launch_bounds__(NTHREADS, 1)
void gemm_mma_kernel(const float* __restrict__ x,
                     const float* __restrict__ bias,
                     const float* __restrict__ conv_w,
                     const float* __restrict__ conv_b,
                     float* __restrict__ out) {
    extern __shared__ char dsm[];
    __shared__ float s_bias2[TN];
    __shared__ float s_cw[TN * 5];

    const int tid  = threadIdx.x;
    const int wid  = tid >> 5;
    const int lane = tid & 31;

    const int n0 = blockIdx.x * TN;          // output-channel base
    const int m0 = blockIdx.y * TM;          // flattened (b*SEQ + t) base
    const int b_ = m0 >> 12;
    const int t0 = m0 & (SEQ - 1);

    const int wm = (wid & 1) * 64;           // 2 warps in M
    const int wn = (wid >> 1) * 64;          // 4 warps in N

    const uint32_t sbase = smem_u32(dsm);

    // epilogue constants
    for (int i = tid; i < TN; i += NTHREADS) {
        const int e = n0 + i;
        s_bias2[i] = bias[e] + conv_b[e];
#pragma unroll
        for (int k = 0; k < 5; k++) s_cw[i * 5 + k] = conv_w[e * 5 + k];
    }

    const char* Ahi = (const char*)(g_Shi + (size_t)m0 * DM);
    const char* Alo = (const char*)(g_Slo + (size_t)m0 * DM);
    const char* Bhi = (const char*)(g_Whi + (size_t)n0 * DM);
    const char* Blo = (const char*)(g_Wlo + (size_t)n0 * DM);

    float acc[4][8][4];
#pragma unroll
    for (int mt = 0; mt < 4; mt++)
#pragma unroll
        for (int nt = 0; nt < 8; nt++)
#pragma unroll
            for (int k = 0; k < 4; k++) acc[mt][nt][k] = 0.0f;

    // ldmatrix lane constants
    const int lr = lane & 15;
    const int lh = lane >> 4;
    const uint32_t xorv = (uint32_t)((lr & 7) << 4);

    // prologue: stage 0
    copy_tile_async(Ahi, sbase + A_HI, TM, tid);
    copy_tile_async(Alo, sbase + A_LO, TM, tid);
    copy_tile_async(Bhi, sbase + B_HI, TN, tid);
    copy_tile_async(Blo, sbase + B_LO, TN, tid);
    CP_COMMIT();

#pragma unroll 1
    for (int kc = 0; kc < NKC; kc++) {
        if (kc + 1 < NKC) {
            const uint32_t nb = sbase + (uint32_t)((kc + 1) & 1) * STAGE;
            const size_t co = (size_t)(kc + 1) * 128;   // byte col offset
            copy_tile_async(Ahi + co, nb + A_HI, TM, tid);
            copy_tile_async(Alo + co, nb + A_LO, TM, tid);
            copy_tile_async(Bhi + co, nb + B_HI, TN, tid);
            copy_tile_async(Blo + co, nb + B_LO, TN, tid);
            CP_COMMIT();
            CP_WAIT(1);
        } else {
            CP_WAIT(0);
        }
        __syncthreads();

        const uint32_t sb = sbase + (uint32_t)(kc & 1) * STAGE;

#pragma unroll
        for (int ks = 0; ks < 4; ks++) {
            // A fragments: 4 m16 tiles, hi+lo
            uint32_t ah[4][4], al[4][4];
#pragma unroll
            for (int mt = 0; mt < 4; mt++) {
                const uint32_t row = (uint32_t)(wm + mt * 16 + lr);
                uint32_t off = (row << 7) + (uint32_t)(ks * 32 + (lh << 4));
                off ^= xorv;
                ldsm_x4(ah[mt], sb + A_HI + off);
                ldsm_x4(al[mt], sb + A_LO + off);
            }
            // B: load per 16-col group, consume immediately (keeps regs low)
#pragma unroll
            for (int p = 0; p < 4; p++) {
                const uint32_t row = (uint32_t)(wn + p * 16 + lr);
                uint32_t off = (row << 7) + (uint32_t)(ks * 32 + (lh << 4));
                off ^= xorv;
                uint32_t r0[4], r1[4];
                uint32_t bh0[2], bh1[2], bl0[2], bl1[2];
                ldsm_x4(r0, sb + B_HI + off);
                bh0[0] = r0[0]; bh0[1] = r0[2];
                bh1[0] = r0[1]; bh1[1] = r0[3];
                ldsm_x4(r1, sb + B_LO + off);
                bl0[0] = r1[0]; bl0[1] = r1[2];
                bl1[0] = r1[1]; bl1[1] = r1[3];
#pragma unroll
                for (int mt = 0; mt < 4; mt++) {
                    float* c0 = acc[mt][2 * p];
                    float* c1 = acc[mt][2 * p + 1];
                    mma_bf16(c0, ah[mt], bh0);
                    mma_bf16(c1, ah[mt], bh1);
                    mma_bf16(c0, al[mt], bh0);
                    mma_bf16(c1, al[mt], bh1);
                    mma_bf16(c0, ah[mt], bl0);
                    mma_bf16(c1, ah[mt], bl1);
                }
            }
        }
        __syncthreads();
    }

    // --- epilogue: + bias + conv_b + depthwise conv(x, K=5), write out -----
    const int lq = lane >> 2;        // 0..7
    const int lc = (lane & 3) * 2;   // col pair within n8 tile
    const float* xb = x + (size_t)b_ * SEQ * DM;

#pragma unroll
    for (int mt = 0; mt < 4; mt++) {
#pragma unroll
        for (int half = 0; half < 2; half++) {
            const int t = t0 + wm + mt * 16 + lq + half * 8;
            float2 v[8];
#pragma unroll
            for (int nt = 0; nt < 8; nt++) {
                const int ei = wn + nt * 8 + lc;
                v[nt].x = acc[mt][nt][half * 2 + 0] + s_bias2[ei];
                v[nt].y = acc[mt][nt][half * 2 + 1] + s_bias2[ei + 1];
            }
#pragma unroll
            for (int k = 0; k < 5; k++) {
                const int tt = t - 2 + k;
                if (tt >= 0 && tt < SEQ) {
                    const float* xr = xb + (size_t)tt * DM + n0;
#pragma unroll
                    for (int nt = 0; nt < 8; nt++) {
                        const int ei = wn + nt * 8 + lc;
                        const float2 xv = *(const float2*)(xr + ei);
                        v[nt].x += s_cw[ei * 5 + k] * xv.x;
                        v[nt].y += s_cw[(ei + 1) * 5 + k] * xv.y;
                    }
                }
            }
            float* op = out + ((size_t)b_ * SEQ + (size_t)t) * DM + n0;
#pragma unroll
            for (int nt = 0; nt < 8; nt++)
                *(float2*)(op + wn + nt * 8 + lc) = v[nt];
        }
    }
}

// ---------------------------------------------------------------------------
extern "C" void kernel_launch(void* const* d_in, const int* in_sizes, int n_in,
                              void* d_out, int out_size) {
    const float* x      = (const float*)d_in[0];
    const float* dl     = (const float*)d_in[1];
    const float* W      = (const float*)d_in[2];
    const float* bias   = (const float*)d_in[3];
    const float* conv_w = (const float*)d_in[4];
    const float* conv_b = (const float*)d_in[5];
    float* out = (float*)d_out;

    cudaFuncSetAttribute(gemm_mma_kernel,
                         cudaFuncAttributeMaxDynamicSharedMemorySize, SMEM_DYN);

    wsplit_kernel<<<(DM * DM) / 256, 256>>>(W);
    ema_partial_kernel<<<BATCH * NC, DM>>>(x, dl);
    ema_carry_kernel<<<BATCH, DM>>>(dl);
    ema_final_kernel<<<BATCH * NC, DM>>>(x, dl);

    dim3 grid(DM / TN, (BATCH * SEQ) / TM);   // (4, 256)
    gemm_mma_kernel<<<grid, NTHREADS, SMEM_DYN>>>(x, bias, conv_w, conv_b, out);
}

// round 6
// speedup vs baseline: 3.0373x; 1.0534x over previous
#include <cuda_runtime.h>
#include <cuda_bf16.h>
#include <cstdint>

#define BATCH 8
#define SEQ   4096
#define DM    1024
#define CHUNK 128
#define NC    (SEQ / CHUNK)   // 32

// GEMM tiling: CTA 128x256, warp 64x64 (2M x 4N warps)
#define TM 128
#define TN 256
#define KC 64                  // bf16 per K stage = 128 bytes per row
#define NKC (DM / KC)          // 16 stages
#define NTHREADS 256

#define A_TILE_BYTES 16384     // 128 rows x 128B
#define B_TILE_BYTES 32768     // 256 rows x 128B

// smem stage layout (per buffer): Ahi 16K | Alo 16K | Bhi 32K | Blo 32K
#define A_HI  0
#define A_LO  16384
#define B_HI  32768
#define B_LO  65536
#define STAGE 98304
#define SMEM_DYN (2 * STAGE)   // 192 KB

// ------------- scratch: TILED + PRE-SWIZZLED layouts (bytes) ---------------
// A tiles: [m_tile(256)][k_stage(16)] -> 16 KB contiguous, rows XOR-swizzled
__device__ char g_Shi_t[(size_t)256 * NKC * A_TILE_BYTES];
__device__ char g_Slo_t[(size_t)256 * NKC * A_TILE_BYTES];
// B tiles: [n_tile(4)][k_stage(16)] -> 32 KB contiguous
__device__ char g_Whi_t[(size_t)4 * NKC * B_TILE_BYTES];
__device__ char g_Wlo_t[(size_t)4 * NKC * B_TILE_BYTES];
__device__ float g_partial[BATCH * NC * DM];
__device__ float g_carry[BATCH * NC * DM];

static __device__ __forceinline__ float sigmoidf_(float v) {
    return 1.0f / (1.0f + expf(-v));
}

// swizzled byte offset within a 128B row: chunk (c8 = col/8 bf16) XOR row&7
static __device__ __forceinline__ uint32_t sw_off(uint32_t row, uint32_t col) {
    // col in bf16 elements (0..63) within the 64-col stage row
    return (row << 7) + ((((col >> 3) ^ (row & 7)) << 4) + ((col & 7) << 1));
}

// ====================== baseline-PTX helpers ================================
__device__ __forceinline__ uint32_t smem_u32(const void* p) {
    uint32_t a;
    asm("{ .reg .u64 t; cvta.to.shared.u64 t, %1; cvt.u32.u64 %0, t; }" : "=r"(a) : "l"(p));
    return a;
}

#define MBARRIER_INIT(addr, count) \
    asm volatile("mbarrier.init.shared.b64 [%0], %1;" :: "r"((uint32_t)(addr)), "r"((uint32_t)(count)) : "memory")

#define MBARRIER_EXPECT_TX(addr, bytes) \
    asm volatile("mbarrier.arrive.expect_tx.shared.b64 _, [%0], %1;" \
        :: "r"((uint32_t)(addr)), "r"((uint32_t)(bytes)) : "memory")

#define MBARRIER_WAIT_PARITY(addr, parity) do { \
    uint32_t _mbar = (uint32_t)(addr); \
    uint32_t _par  = (uint32_t)(parity); \
    uint32_t _done; \
    asm volatile("{\n\t.reg .pred p;\n\t" \
        "mbarrier.try_wait.parity.acquire.cta.shared::cta.b64 p, [%1], %2;\n\t" \
        "selp.b32 %0, 1, 0, p;\n\t}" : "=r"(_done) : "r"(_mbar), "r"(_par) : "memory"); \
    if (!_done) { \
        asm volatile("{\n\t.reg .pred P1;\n\t" \
            "WL_%=:\n\t" \
            "mbarrier.try_wait.parity.acquire.cta.shared::cta.b64 P1, [%0], %1, 0x989680;\n\t" \
            "@P1 bra.uni WD_%=;\n\t" \
            "bra.uni WL_%=;\n\t" \
            "WD_%=:\n\t}" :: "r"(_mbar), "r"(_par) : "memory"); \
    } \
} while (0)

__device__ __forceinline__ void bulk_g2s(uint32_t dst, const void* src,
                                         uint32_t bytes, uint32_t mbar) {
    asm volatile(
        "cp.async.bulk.shared::cluster.global.mbarrier::complete_tx::bytes [%0], [%1], %2, [%3];"
        :: "r"(dst), "l"(src), "r"(bytes), "r"(mbar) : "memory");
}

__device__ __forceinline__ void ldsm_x4(uint32_t* r, uint32_t addr) {
    asm volatile("ldmatrix.sync.aligned.m8n8.x4.shared.b16 {%0,%1,%2,%3}, [%4];"
                 : "=r"(r[0]), "=r"(r[1]), "=r"(r[2]), "=r"(r[3]) : "r"(addr));
}

__device__ __forceinline__ void mma_bf16(float* c, const uint32_t* a, const uint32_t* b) {
    asm volatile(
        "mma.sync.aligned.m16n8k16.row.col.f32.bf16.bf16.f32 "
        "{%0,%1,%2,%3}, {%4,%5,%6,%7}, {%8,%9}, {%0,%1,%2,%3};"
        : "+f"(c[0]), "+f"(c[1]), "+f"(c[2]), "+f"(c[3])
        : "r"(a[0]), "r"(a[1]), "r"(a[2]), "r"(a[3]), "r"(b[0]), "r"(b[1]));
}

// ====================== prep: EMA partial + W split (merged launch) =========
__global__ void prep_kernel(const float* __restrict__ x,
                            const float* __restrict__ dl,
                            const float* __restrict__ W) {
    const int tid = threadIdx.x;           // 1024
    if (blockIdx.x < BATCH * NC) {
        // --- EMA partial scan (zero-seeded chunk) ---
        const int d  = tid;
        const int bc = blockIdx.x;
        const int b  = bc / NC;
        const int c  = bc % NC;
        const float a  = sigmoidf_(dl[d]);
        const float om = 1.0f - a;
        const float* xp = x + ((size_t)b * SEQ + (size_t)c * CHUNK) * DM + d;
        float s = 0.0f;
#pragma unroll 4
        for (int i = 0; i < CHUNK; i++) s = a * s + om * xp[(size_t)i * DM];
        g_partial[(size_t)bc * DM + d] = s;
    } else {
        // --- W hi/lo split into tiled swizzled layout ---
        const size_t i = ((size_t)(blockIdx.x - BATCH * NC)) * 1024 + tid;
        const uint32_t e = (uint32_t)(i >> 10);      // W row (out channel)
        const uint32_t d = (uint32_t)(i & 1023);
        const float w = W[i];
        const __nv_bfloat16 h = __float2bfloat16_rn(w);
        const __nv_bfloat16 l = __float2bfloat16_rn(w - __bfloat162float(h));
        const uint32_t nt = e >> 8;                  // 256-row tile
        const uint32_t r  = e & 255;
        const uint32_t kc = d >> 6;
        const uint32_t cc = d & 63;
        const size_t off = ((size_t)(nt * NKC + kc)) * B_TILE_BYTES + sw_off(r, cc);
        *(__nv_bfloat16*)(g_Whi_t + off) = h;
        *(__nv_bfloat16*)(g_Wlo_t + off) = l;
    }
}

// ====================== EMA carry combine ===================================
__global__ void ema_carry_kernel(const float* __restrict__ dl) {
    const int d = threadIdx.x;
    const int b = blockIdx.x;
    const float a = sigmoidf_(dl[d]);
    float pw = a;
#pragma unroll
    for (int i = 0; i < 7; i++) pw *= pw;   // a^128
    float cur = 0.0f;
    for (int c = 0; c < NC; c++) {
        const size_t idx = ((size_t)b * NC + c) * DM + d;
        g_carry[idx] = cur;
        cur = pw * cur + g_partial[idx];
    }
}

// ====================== EMA final: seeded rescan -> tiled bf16 hi/lo ========
__global__ void ema_final_kernel(const float* __restrict__ x,
                                 const float* __restrict__ dl) {
    const int d  = threadIdx.x;
    const int bc = blockIdx.x;
    const int b  = bc / NC;
    const int c  = bc % NC;
    const float a  = sigmoidf_(dl[d]);
    const float om = 1.0f - a;
    float s = g_carry[(size_t)bc * DM + d];
    const float* xp = x + ((size_t)b * SEQ + (size_t)c * CHUNK) * DM + d;

    // chunk is exactly one 128-row m-tile: mt fixed, r = i
    const uint32_t mt = (uint32_t)((b * SEQ + c * CHUNK) >> 7);
    const uint32_t kc = (uint32_t)d >> 6;
    const uint32_t cc = (uint32_t)d & 63;
    const size_t tbase = ((size_t)(mt * NKC + kc)) * A_TILE_BYTES;

#pragma unroll 4
    for (int i = 0; i < CHUNK; i++) {
        s = a * s + om * xp[(size_t)i * DM];
        const __nv_bfloat16 h = __float2bfloat16_rn(s);
        const size_t off = tbase + sw_off((uint32_t)i, cc);
        *(__nv_bfloat16*)(g_Shi_t + off) = h;
        *(__nv_bfloat16*)(g_Slo_t + off) = __float2bfloat16_rn(s - __bfloat162float(h));
    }
}

// ====================== HMMA GEMM, bulk-copy pipeline, fused conv ===========
__global__ __launch_bounds__(NTHREADS, 1)
void gemm_mma_kernel(const float* __restrict__ x,
                     const float* __restrict__ bias,
                     const float* __restrict__ conv_w,
                     const float* __restrict__ conv_b,
                     float* __restrict__ out) {
    extern __shared__ __align__(128) char dsm[];
    __shared__ __align__(8) unsigned long long s_full[2];
    __shared__ float s_bias2[TN];
    __shared__ float s_cw[TN * 5];

    const int tid  = threadIdx.x;
    const int wid  = tid >> 5;
    const int lane = tid & 31;

    const int nt = blockIdx.x;               // 0..3  (TN=256 tile of W)
    const int mt = blockIdx.y;               // 0..255 (TM=128 tile of S)
    const int n0 = nt * TN;
    const int m0 = mt * TM;
    const int b_ = m0 >> 12;
    const int t0 = m0 & (SEQ - 1);

    const int wm = (wid & 1) * 64;
    const int wn = (wid >> 1) * 64;

    const uint32_t sbase = smem_u32(dsm);
    const uint32_t fb0 = smem_u32(&s_full[0]);
    const uint32_t fb1 = smem_u32(&s_full[1]);

    if (tid == 0) {
        MBARRIER_INIT(fb0, 1);
        MBARRIER_INIT(fb1, 1);
    }
    // epilogue constants
    for (int i = tid; i < TN; i += NTHREADS) {
        const int e = n0 + i;
        s_bias2[i] = bias[e] + conv_b[e];
#pragma unroll
        for (int k = 0; k < 5; k++) s_cw[i * 5 + k] = conv_w[e * 5 + k];
    }
    __syncthreads();

    // prologue: stage 0 -> buf 0
    if (tid == 0) {
        MBARRIER_EXPECT_TX(fb0, STAGE);
        bulk_g2s(sbase + A_HI, g_Shi_t + (size_t)(mt * NKC) * A_TILE_BYTES, A_TILE_BYTES, fb0);
        bulk_g2s(sbase + A_LO, g_Slo_t + (size_t)(mt * NKC) * A_TILE_BYTES, A_TILE_BYTES, fb0);
        bulk_g2s(sbase + B_HI, g_Whi_t + (size_t)(nt * NKC) * B_TILE_BYTES, B_TILE_BYTES, fb0);
        bulk_g2s(sbase + B_LO, g_Wlo_t + (size_t)(nt * NKC) * B_TILE_BYTES, B_TILE_BYTES, fb0);
    }

    float acc[4][8][4];
#pragma unroll
    for (int mtt = 0; mtt < 4; mtt++)
#pragma unroll
        for (int ntt = 0; ntt < 8; ntt++)
#pragma unroll
            for (int k = 0; k < 4; k++) acc[mtt][ntt][k] = 0.0f;

    const int lr = lane & 15;
    const int lh = lane >> 4;
    const uint32_t xorv = (uint32_t)((lr & 7) << 4);

    int ph0 = 0, ph1 = 0;

#pragma unroll 1
    for (int kc = 0; kc < NKC; kc++) {
        const int cur = kc & 1;

        // issue next stage into the other buffer (freed at end of iter kc-1)
        if (kc + 1 < NKC && tid == 0) {
            const uint32_t nb   = sbase + (uint32_t)(cur ^ 1) * STAGE;
            const uint32_t nbar = (cur ^ 1) ? fb1 : fb0;
            MBARRIER_EXPECT_TX(nbar, STAGE);
            bulk_g2s(nb + A_HI, g_Shi_t + (size_t)(mt * NKC + kc + 1) * A_TILE_BYTES, A_TILE_BYTES, nbar);
            bulk_g2s(nb + A_LO, g_Slo_t + (size_t)(mt * NKC + kc + 1) * A_TILE_BYTES, A_TILE_BYTES, nbar);
            bulk_g2s(nb + B_HI, g_Whi_t + (size_t)(nt * NKC + kc + 1) * B_TILE_BYTES, B_TILE_BYTES, nbar);
            bulk_g2s(nb + B_LO, g_Wlo_t + (size_t)(nt * NKC + kc + 1) * B_TILE_BYTES, B_TILE_BYTES, nbar);
        }

        if (cur == 0) { MBARRIER_WAIT_PARITY(fb0, ph0); ph0 ^= 1; }
        else          { MBARRIER_WAIT_PARITY(fb1, ph1); ph1 ^= 1; }

        const uint32_t sb = sbase + (uint32_t)cur * STAGE;

#pragma unroll
        for (int ks = 0; ks < 4; ks++) {
            uint32_t ah[4][4], al[4][4];
#pragma unroll
            for (int mtt = 0; mtt < 4; mtt++) {
                const uint32_t row = (uint32_t)(wm + mtt * 16 + lr);
                uint32_t off = (row << 7) + (uint32_t)(ks * 32 + (lh << 4));
                off ^= xorv;
                ldsm_x4(ah[mtt], sb + A_HI + off);
                ldsm_x4(al[mtt], sb + A_LO + off);
            }
#pragma unroll
            for (int p = 0; p < 4; p++) {
                const uint32_t row = (uint32_t)(wn + p * 16 + lr);
                uint32_t off = (row << 7) + (uint32_t)(ks * 32 + (lh << 4));
                off ^= xorv;
                uint32_t r0[4], r1[4];
                uint32_t bh0[2], bh1[2], bl0[2], bl1[2];
                ldsm_x4(r0, sb + B_HI + off);
                bh0[0] = r0[0]; bh0[1] = r0[2];
                bh1[0] = r0[1]; bh1[1] = r0[3];
                ldsm_x4(r1, sb + B_LO + off);
                bl0[0] = r1[0]; bl0[1] = r1[2];
                bl1[0] = r1[1]; bl1[1] = r1[3];
#pragma unroll
                for (int mtt = 0; mtt < 4; mtt++) {
                    float* c0 = acc[mtt][2 * p];
                    float* c1 = acc[mtt][2 * p + 1];
                    mma_bf16(c0, ah[mtt], bh0);
                    mma_bf16(c1, ah[mtt], bh1);
                    mma_bf16(c0, al[mtt], bh0);
                    mma_bf16(c1, al[mtt], bh1);
                    mma_bf16(c0, ah[mtt], bl0);
                    mma_bf16(c1, ah[mtt], bl1);
                }
            }
        }
        __syncthreads();   // all warps done reading buf `cur` -> reusable
    }

    // --- epilogue: + bias + conv_b + depthwise conv(x, K=5), write out -----
    const int lq = lane >> 2;
    const int lc = (lane & 3) * 2;
    const float* xb = x + (size_t)b_ * SEQ * DM;

#pragma unroll
    for (int mtt = 0; mtt < 4; mtt++) {
#pragma unroll
        for (int half = 0; half < 2; half++) {
            const int t = t0 + wm + mtt * 16 + lq + half * 8;
            float2 v[8];
#pragma unroll
            for (int ntt = 0; ntt < 8; ntt++) {
                const int ei = wn + ntt * 8 + lc;
                v[ntt].x = acc[mtt][ntt][half * 2 + 0] + s_bias2[ei];
                v[ntt].y = acc[mtt][ntt][half * 2 + 1] + s_bias2[ei + 1];
            }
#pragma unroll
            for (int k = 0; k < 5; k++) {
                const int tt = t - 2 + k;
                if (tt >= 0 && tt < SEQ) {
                    const float* xr = xb + (size_t)tt * DM + n0;
#pragma unroll
                    for (int ntt = 0; ntt < 8; ntt++) {
                        const int ei = wn + ntt * 8 + lc;
                        const float2 xv = *(const float2*)(xr + ei);
                        v[ntt].x += s_cw[ei * 5 + k] * xv.x;
                        v[ntt].y += s_cw[(ei + 1) * 5 + k] * xv.y;
                    }
                }
            }
            float* op = out + ((size_t)b_ * SEQ + (size_t)t) * DM + n0;
#pragma unroll
            for (int ntt = 0; ntt < 8; ntt++)
                *(float2*)(op + wn + ntt * 8 + lc) = v[ntt];
        }
    }
}

// ---------------------------------------------------------------------------
extern "C" void kernel_launch(void* const* d_in, const int* in_sizes, int n_in,
                              void* d_out, int out_size) {
    const float* x      = (const float*)d_in[0];
    const float* dl     = (const float*)d_in[1];
    const float* W      = (const float*)d_in[2];
    const float* bias   = (const float*)d_in[3];
    const float* conv_w = (const float*)d_in[4];
    const float* conv_b = (const float*)d_in[5];
    float* out = (float*)d_out;

    cudaFuncSetAttribute(gemm_mma_kernel,
                         cudaFuncAttributeMaxDynamicSharedMemorySize, SMEM_DYN);

    prep_kernel<<<BATCH * NC + (DM * DM) / 1024, 1024>>>(x, dl, W);
    ema_carry_kernel<<<BATCH, DM>>>(dl);
    ema_final_kernel<<<BATCH * NC, DM>>>(x, dl);

    dim3 grid(DM / TN, (BATCH * SEQ) / TM);   // (4, 256)
    gemm_mma_kernel<<<grid, NTHREADS, SMEM_DYN>>>(x, bias, conv_w, conv_b, out);
}